// round 1
// baseline (speedup 1.0000x reference)
#include <cuda_runtime.h>
#include <cstdint>

#define DT 0.1f
#define TAU_HP 12.3f
#define TAU_LP 2.3f

#define N_NEURONS_MAX 200000
#define N_EDGES_MAX   6400000
#define N_TM1_CONST   25000

// ---------------- device scratch (no allocations allowed) ----------------
__device__ int   g_counts[N_NEURONS_MAX];       // histogram, then scatter cursor
__device__ int   g_row_ptr[N_NEURONS_MAX + 1];  // CSR row pointers (by target)
__device__ int   g_block_sums[512];             // scan partials
__device__ int2  g_edges[N_EDGES_MAX];          // interleaved {source_idx, weight_bits}
__device__ float g_v[N_NEURONS_MAX];            // membrane potential
__device__ float g_r[N_NEURONS_MAX];            // relu(v1), gather source
__device__ float g_f[N_TM1_CONST];              // Tm1 high-pass state
__device__ float g_tv[N_TM1_CONST];             // Tm1 low-pass state

// ---------------- kernels ----------------

__global__ void k_init(int n_neurons, int n_tm1) {
    int i = blockIdx.x * blockDim.x + threadIdx.x;
    if (i < n_neurons) { g_counts[i] = 0; g_v[i] = 0.0f; }
    if (i < n_tm1)     { g_f[i] = 0.0f; g_tv[i] = 0.0f; }
}

// histogram of edges per target, skipping targets < n_tm1 (their syn is dead)
__global__ void k_hist(const int* __restrict__ tgt, int n_edges, int n_tm1) {
    int e = blockIdx.x * blockDim.x + threadIdx.x;
    if (e >= n_edges) return;
    int t = tgt[e];
    if (t >= n_tm1) atomicAdd(&g_counts[t], 1);
}

// block-local exclusive scan (block = 1024 elems)
__global__ void k_scan1(int n) {
    __shared__ int sh[1024];
    int tid = threadIdx.x;
    int i = blockIdx.x * 1024 + tid;
    int c = (i < n) ? g_counts[i] : 0;
    sh[tid] = c;
    __syncthreads();
    #pragma unroll
    for (int o = 1; o < 1024; o <<= 1) {
        int t = (tid >= o) ? sh[tid - o] : 0;
        __syncthreads();
        sh[tid] += t;
        __syncthreads();
    }
    int incl = sh[tid];
    if (i < n) g_row_ptr[i] = incl - c;           // exclusive within block
    if (tid == 1023) g_block_sums[blockIdx.x] = incl;
}

__global__ void k_scan2(int nblocks) {
    if (threadIdx.x == 0 && blockIdx.x == 0) {
        int acc = 0;
        for (int b = 0; b < nblocks; b++) {
            int t = g_block_sums[b];
            g_block_sums[b] = acc;
            acc += t;
        }
        g_block_sums[nblocks] = acc;   // total kept edges
    }
}

__global__ void k_scan3(int n, int nblocks) {
    int i = blockIdx.x * blockDim.x + threadIdx.x;
    if (i < n) {
        int rp = g_row_ptr[i] + g_block_sums[i >> 10];
        g_row_ptr[i] = rp;
        g_counts[i]  = rp;             // cursor for the scatter fill
    }
    if (i == 0) g_row_ptr[n] = g_block_sums[nblocks];
}

// scatter edges into CSR slots, interleaving src+weight into one 8B record
__global__ void k_fill(const int* __restrict__ src, const int* __restrict__ tgt,
                       const float* __restrict__ w, int n_edges, int n_tm1) {
    int e = blockIdx.x * blockDim.x + threadIdx.x;
    if (e >= n_edges) return;
    int t = tgt[e];
    if (t >= n_tm1) {
        int pos = atomicAdd(&g_counts[t], 1);
        g_edges[pos] = make_int2(src[e], __float_as_int(w[e]));
    }
}

// per-step: Tm1 filter update + r = relu(v1)
__global__ void k_stepA(const float* __restrict__ x, int n_neurons, int n_tm1) {
    int i = blockIdx.x * blockDim.x + threadIdx.x;
    if (i >= n_neurons) return;
    if (i < n_tm1) {
        float f = g_f[i], tv = g_tv[i], xi = x[i];
        float hp = xi - f;
        g_f[i] = f + DT * hp / TAU_HP;
        g_v[i] = tv;                        // v1[:n_tm1] = old tm1_v
        g_r[i] = fmaxf(tv, 0.0f);
        float rect = fmaxf(hp, 0.0f);
        g_tv[i] = tv + DT * (rect - tv) / TAU_LP;
    } else {
        g_r[i] = fmaxf(g_v[i], 0.0f);
    }
}

// per-step: warp-per-row SpMV + Euler update (rows >= n_tm1 only)
__global__ void k_stepB(const float* __restrict__ tau, const float* __restrict__ vrest,
                        int n_neurons, int n_tm1) {
    int gw = (blockIdx.x * blockDim.x + threadIdx.x) >> 5;
    int lane = threadIdx.x & 31;
    int row = n_tm1 + gw;
    if (row >= n_neurons) return;
    int s = g_row_ptr[row];
    int e = g_row_ptr[row + 1];
    float sum = 0.0f;
    for (int j = s + lane; j < e; j += 32) {
        int2 ed = g_edges[j];
        sum += __int_as_float(ed.y) * __ldg(&g_r[ed.x]);
    }
    #pragma unroll
    for (int o = 16; o; o >>= 1) sum += __shfl_xor_sync(0xffffffffu, sum, o);
    if (lane == 0) {
        float vv = g_v[row];
        // dv = (-v + syn + vrest)/tau ; v += DT*dv   (external is dead code)
        g_v[row] = vv + DT * ((sum - vv + vrest[row]) / tau[row]);
    }
}

__global__ void k_out(float* __restrict__ out, int n) {
    int i = blockIdx.x * blockDim.x + threadIdx.x;
    if (i < n) out[i] = g_v[i];
}

// ---------------- launch ----------------

extern "C" void kernel_launch(void* const* d_in, const int* in_sizes, int n_in,
                              void* d_out, int out_size) {
    const float* tm1_input = (const float*)d_in[0];   // [steps, n_tm1]
    const float* weights   = (const float*)d_in[1];   // [n_edges]
    const float* tau       = (const float*)d_in[2];   // [n_neurons]
    const float* vrest     = (const float*)d_in[3];   // [n_neurons]
    const int*   src       = (const int*)  d_in[4];   // [n_edges]
    const int*   tgt       = (const int*)  d_in[5];   // [n_edges]

    const int n_tm1     = N_TM1_CONST;
    const int n_edges   = in_sizes[1];
    const int n_neurons = in_sizes[2];
    const int steps     = in_sizes[0] / n_tm1;

    const int TPB = 256;
    int nb_neu  = (n_neurons + TPB - 1) / TPB;
    int nb_edge = (n_edges + TPB - 1) / TPB;
    int scan_blocks = (n_neurons + 1023) / 1024;

    // one-time (per launch) CSR build by target
    k_init<<<nb_neu, TPB>>>(n_neurons, n_tm1);
    k_hist<<<nb_edge, TPB>>>(tgt, n_edges, n_tm1);
    k_scan1<<<scan_blocks, 1024>>>(n_neurons);
    k_scan2<<<1, 32>>>(scan_blocks);
    k_scan3<<<nb_neu, TPB>>>(n_neurons, scan_blocks);
    k_fill<<<nb_edge, TPB>>>(src, tgt, weights, n_edges, n_tm1);

    // time loop
    int rows = n_neurons - n_tm1;
    long long threadsB = (long long)rows * 32;
    int nb_B = (int)((threadsB + TPB - 1) / TPB);
    for (int s = 0; s < steps; s++) {
        k_stepA<<<nb_neu, TPB>>>(tm1_input + (long long)s * n_tm1, n_neurons, n_tm1);
        k_stepB<<<nb_B, TPB>>>(tau, vrest, n_neurons, n_tm1);
    }

    k_out<<<(out_size + TPB - 1) / TPB, TPB>>>((float*)d_out, out_size);
}

// round 2
// speedup vs baseline: 1.6316x; 1.6316x over previous
#include <cuda_runtime.h>
#include <cstdint>

#define DT 0.1f
#define TAU_HP 12.3f
#define TAU_LP 2.3f

#define N_NEURONS_MAX 200000
#define N_EDGES_MAX   6400000
#define N_TM1_MAX     25000
#define STEPS_MAX     50

// ---------------- device scratch (no allocations allowed) ----------------
__device__ int   g_counts[N_NEURONS_MAX];         // histogram, then scatter cursor
__device__ int   g_row_ptr[N_NEURONS_MAX + 1];    // CSR row pointers (by target)
__device__ int   g_block_sums[512];               // scan partials
__device__ int2  g_edges[N_EDGES_MAX];            // interleaved {source_idx, weight_bits}
__device__ float g_vbuf[2][N_NEURONS_MAX];        // double-buffered membrane potential
__device__ float g_table[(STEPS_MAX + 1) * N_TM1_MAX]; // tm1_v_old(s) for every step

// ---------------- kernels ----------------

__global__ void k_init(int n_neurons) {
    int i = blockIdx.x * blockDim.x + threadIdx.x;
    if (i < n_neurons) { g_counts[i] = 0; g_vbuf[0][i] = 0.0f; }
}

// Precompute Tm1 low-pass state trajectory. table[s] = tm1_v state entering step s.
__global__ void k_tm1(const float* __restrict__ x, int n_tm1, int steps) {
    int i = blockIdx.x * blockDim.x + threadIdx.x;
    if (i >= n_tm1) return;
    float f = 0.0f, tv = 0.0f;
    for (int s = 0; s < steps; s++) {
        g_table[s * n_tm1 + i] = tv;
        float xi = x[(long long)s * n_tm1 + i];
        float hp = xi - f;
        f  += DT * hp / TAU_HP;
        tv += DT * (fmaxf(hp, 0.0f) - tv) / TAU_LP;
    }
    g_table[steps * n_tm1 + i] = tv;
}

// histogram of edges per target, skipping targets < n_tm1 (their synaptic sum is dead)
__global__ void k_hist(const int* __restrict__ tgt, int n_edges, int n_tm1) {
    int e = blockIdx.x * blockDim.x + threadIdx.x;
    if (e >= n_edges) return;
    int t = tgt[e];
    if (t >= n_tm1) atomicAdd(&g_counts[t], 1);
}

__global__ void k_scan1(int n) {
    __shared__ int sh[1024];
    int tid = threadIdx.x;
    int i = blockIdx.x * 1024 + tid;
    int c = (i < n) ? g_counts[i] : 0;
    sh[tid] = c;
    __syncthreads();
    #pragma unroll
    for (int o = 1; o < 1024; o <<= 1) {
        int t = (tid >= o) ? sh[tid - o] : 0;
        __syncthreads();
        sh[tid] += t;
        __syncthreads();
    }
    int incl = sh[tid];
    if (i < n) g_row_ptr[i] = incl - c;
    if (tid == 1023) g_block_sums[blockIdx.x] = incl;
}

__global__ void k_scan2(int nblocks) {
    if (threadIdx.x == 0 && blockIdx.x == 0) {
        int acc = 0;
        for (int b = 0; b < nblocks; b++) {
            int t = g_block_sums[b];
            g_block_sums[b] = acc;
            acc += t;
        }
        g_block_sums[nblocks] = acc;
    }
}

__global__ void k_scan3(int n, int nblocks) {
    int i = blockIdx.x * blockDim.x + threadIdx.x;
    if (i < n) {
        int rp = g_row_ptr[i] + g_block_sums[i >> 10];
        g_row_ptr[i] = rp;
        g_counts[i]  = rp;
    }
    if (i == 0) g_row_ptr[n] = g_block_sums[nblocks];
}

__global__ void k_fill(const int* __restrict__ src, const int* __restrict__ tgt,
                       const float* __restrict__ w, int n_edges, int n_tm1) {
    int e = blockIdx.x * blockDim.x + threadIdx.x;
    if (e >= n_edges) return;
    int t = tgt[e];
    if (t >= n_tm1) {
        int pos = atomicAdd(&g_counts[t], 1);
        g_edges[pos] = make_int2(src[e], __float_as_int(w[e]));
    }
}

// Fused per-step kernel: first `copy_blocks` blocks refresh the Tm1 slice of
// v_new from the precomputed table; the rest do the SpMV with 8 lanes/row and
// relu applied inline on the gather (r never materialized).
__global__ void k_step(const float* __restrict__ vold, float* __restrict__ vnew,
                       const float* __restrict__ table_next,
                       const float* __restrict__ tau, const float* __restrict__ vrest,
                       int n_neurons, int n_tm1, int copy_blocks) {
    int bid = blockIdx.x;
    if (bid < copy_blocks) {
        int i = bid * blockDim.x + threadIdx.x;
        if (i < n_tm1) vnew[i] = table_next[i];
        return;
    }
    int group = threadIdx.x >> 3;        // 32 groups of 8 lanes per 256-thread block
    int lane8 = threadIdx.x & 7;
    int row = n_tm1 + (bid - copy_blocks) * 32 + group;
    if (row >= n_neurons) return;

    int s = g_row_ptr[row];
    int e = g_row_ptr[row + 1];
    float sum = 0.0f;
    int j = s + lane8;
    // 4-way unrolled: 4 independent gathers in flight per thread
    for (; j + 24 < e; j += 32) {
        int2 e0 = g_edges[j];
        int2 e1 = g_edges[j + 8];
        int2 e2 = g_edges[j + 16];
        int2 e3 = g_edges[j + 24];
        float r0 = fmaxf(__ldg(&vold[e0.x]), 0.0f);
        float r1 = fmaxf(__ldg(&vold[e1.x]), 0.0f);
        float r2 = fmaxf(__ldg(&vold[e2.x]), 0.0f);
        float r3 = fmaxf(__ldg(&vold[e3.x]), 0.0f);
        sum += __int_as_float(e0.y) * r0;
        sum += __int_as_float(e1.y) * r1;
        sum += __int_as_float(e2.y) * r2;
        sum += __int_as_float(e3.y) * r3;
    }
    for (; j < e; j += 8) {
        int2 ed = g_edges[j];
        sum += __int_as_float(ed.y) * fmaxf(__ldg(&vold[ed.x]), 0.0f);
    }
    sum += __shfl_xor_sync(0xffffffffu, sum, 4);
    sum += __shfl_xor_sync(0xffffffffu, sum, 2);
    sum += __shfl_xor_sync(0xffffffffu, sum, 1);
    if (lane8 == 0) {
        float vv = vold[row];
        vnew[row] = vv + DT * ((sum - vv + vrest[row]) / tau[row]);
    }
}

__global__ void k_out(float* __restrict__ out, const float* __restrict__ vfinal,
                      int n, int n_tm1, int steps) {
    int i = blockIdx.x * blockDim.x + threadIdx.x;
    if (i >= n) return;
    out[i] = (i < n_tm1) ? g_table[(steps - 1) * n_tm1 + i] : vfinal[i];
}

// ---------------- launch ----------------

extern "C" void kernel_launch(void* const* d_in, const int* in_sizes, int n_in,
                              void* d_out, int out_size) {
    const float* tm1_input = (const float*)d_in[0];   // [steps, n_tm1]
    const float* weights   = (const float*)d_in[1];   // [n_edges]
    const float* tau       = (const float*)d_in[2];   // [n_neurons]
    const float* vrest     = (const float*)d_in[3];   // [n_neurons]
    const int*   src       = (const int*)  d_in[4];   // [n_edges]
    const int*   tgt       = (const int*)  d_in[5];   // [n_edges]

    const int n_tm1     = 25000;
    const int n_edges   = in_sizes[1];
    const int n_neurons = in_sizes[2];
    const int steps     = in_sizes[0] / n_tm1;

    const int TPB = 256;
    int nb_neu  = (n_neurons + TPB - 1) / TPB;
    int nb_edge = (n_edges + TPB - 1) / TPB;
    int scan_blocks = (n_neurons + 1023) / 1024;

    // one-time (per launch) setup: zero state, Tm1 trajectory, CSR build by target
    k_init<<<nb_neu, TPB>>>(n_neurons);
    k_tm1<<<(n_tm1 + TPB - 1) / TPB, TPB>>>(tm1_input, n_tm1, steps);
    k_hist<<<nb_edge, TPB>>>(tgt, n_edges, n_tm1);
    k_scan1<<<scan_blocks, 1024>>>(n_neurons);
    k_scan2<<<1, 32>>>(scan_blocks);
    k_scan3<<<nb_neu, TPB>>>(n_neurons, scan_blocks);
    k_fill<<<nb_edge, TPB>>>(src, tgt, weights, n_edges, n_tm1);

    // time loop: ONE kernel per step
    int rows = n_neurons - n_tm1;
    int copy_blocks = (n_tm1 + TPB - 1) / TPB;
    int spmv_blocks = (rows + 31) / 32;            // 32 rows per block (8 lanes/row)
    int nb_step = copy_blocks + spmv_blocks;

    float* tbl = nullptr;
    cudaGetSymbolAddress((void**)&tbl, g_table);

    for (int st = 0; st < steps; st++) {
        const float* vold = &g_vbuf[st & 1][0];
        float* vnew = nullptr;
        // device-symbol addresses: take via static mapping
        // (g_vbuf is a __device__ array; use cudaGetSymbolAddress once)
        static float* vbase = nullptr;
        if (!vbase) cudaGetSymbolAddress((void**)&vbase, g_vbuf);
        vold = vbase + (size_t)(st & 1) * N_NEURONS_MAX;
        vnew = vbase + (size_t)((st + 1) & 1) * N_NEURONS_MAX;
        const float* table_next = tbl + (size_t)(st + 1) * n_tm1;
        k_step<<<nb_step, TPB>>>(vold, vnew, table_next, tau, vrest,
                                 n_neurons, n_tm1, copy_blocks);
    }

    static float* vbase2 = nullptr;
    if (!vbase2) cudaGetSymbolAddress((void**)&vbase2, g_vbuf);
    const float* vfinal = vbase2 + (size_t)(steps & 1) * N_NEURONS_MAX;
    k_out<<<(out_size + TPB - 1) / TPB, TPB>>>((float*)d_out, vfinal,
                                               out_size, n_tm1, steps);
}

// round 4
// speedup vs baseline: 1.7489x; 1.0718x over previous
#include <cuda_runtime.h>
#include <cuda_fp16.h>
#include <cstdint>

#define DT 0.1f
#define TAU_HP 12.3f
#define TAU_LP 2.3f

#define N_NEURONS_MAX 200000
#define N_EDGES_MAX   6400000
#define N_TM1_MAX     25000
#define STEPS_MAX     50

// ---------------- device scratch (no allocations allowed) ----------------
__device__ int    g_counts[N_NEURONS_MAX];         // histogram, then scatter cursor
__device__ int    g_row_ptr[N_NEURONS_MAX + 1];    // CSR row pointers (by target)
__device__ int    g_block_sums[512];               // scan partials
__device__ int2   g_edges[N_EDGES_MAX];            // interleaved {source_idx, weight_bits}
__device__ float  g_vbuf[2][N_NEURONS_MAX];        // double-buffered membrane potential (fp32)
__device__ __half g_rbuf[2][N_NEURONS_MAX];        // double-buffered relu(v) in fp16 (gather src)
__device__ float  g_table[(STEPS_MAX + 1) * N_TM1_MAX]; // tm1_v_old(s) for every step

// ---------------- kernels ----------------

__global__ void k_init(int n_neurons) {
    int i = blockIdx.x * blockDim.x + threadIdx.x;
    if (i < n_neurons) {
        g_counts[i]  = 0;
        g_vbuf[0][i] = 0.0f;
        g_rbuf[0][i] = __float2half(0.0f);
    }
}

// Precompute Tm1 low-pass state trajectory. table[s] = tm1_v state entering step s.
__global__ void k_tm1(const float* __restrict__ x, int n_tm1, int steps) {
    int i = blockIdx.x * blockDim.x + threadIdx.x;
    if (i >= n_tm1) return;
    float f = 0.0f, tv = 0.0f;
    for (int s = 0; s < steps; s++) {
        g_table[s * n_tm1 + i] = tv;
        float xi = x[(long long)s * n_tm1 + i];
        float hp = xi - f;
        f  += DT * hp / TAU_HP;
        tv += DT * (fmaxf(hp, 0.0f) - tv) / TAU_LP;
    }
    g_table[steps * n_tm1 + i] = tv;
}

// histogram of edges per target, skipping targets < n_tm1 (their synaptic sum is dead)
__global__ void k_hist(const int* __restrict__ tgt, int n_edges, int n_tm1) {
    int e = blockIdx.x * blockDim.x + threadIdx.x;
    if (e >= n_edges) return;
    int t = tgt[e];
    if (t >= n_tm1) atomicAdd(&g_counts[t], 1);
}

__global__ void k_scan1(int n) {
    __shared__ int sh[1024];
    int tid = threadIdx.x;
    int i = blockIdx.x * 1024 + tid;
    int c = (i < n) ? g_counts[i] : 0;
    sh[tid] = c;
    __syncthreads();
    #pragma unroll
    for (int o = 1; o < 1024; o <<= 1) {
        int t = (tid >= o) ? sh[tid - o] : 0;
        __syncthreads();
        sh[tid] += t;
        __syncthreads();
    }
    int incl = sh[tid];
    if (i < n) g_row_ptr[i] = incl - c;
    if (tid == 1023) g_block_sums[blockIdx.x] = incl;
}

__global__ void k_scan2(int nblocks) {
    if (threadIdx.x == 0 && blockIdx.x == 0) {
        int acc = 0;
        for (int b = 0; b < nblocks; b++) {
            int t = g_block_sums[b];
            g_block_sums[b] = acc;
            acc += t;
        }
        g_block_sums[nblocks] = acc;
    }
}

__global__ void k_scan3(int n, int nblocks) {
    int i = blockIdx.x * blockDim.x + threadIdx.x;
    if (i < n) {
        int rp = g_row_ptr[i] + g_block_sums[i >> 10];
        g_row_ptr[i] = rp;
        g_counts[i]  = rp;
    }
    if (i == 0) g_row_ptr[n] = g_block_sums[nblocks];
}

__global__ void k_fill(const int* __restrict__ src, const int* __restrict__ tgt,
                       const float* __restrict__ w, int n_edges, int n_tm1) {
    int e = blockIdx.x * blockDim.x + threadIdx.x;
    if (e >= n_edges) return;
    int t = tgt[e];
    if (t >= n_tm1) {
        int pos = atomicAdd(&g_counts[t], 1);
        g_edges[pos] = make_int2(src[e], __float_as_int(w[e]));
    }
}

// Fused per-step kernel.
//  - first copy_blocks blocks: refresh Tm1 slice of vnew/rnew from the table
//  - remaining blocks: 8-lane-per-row SpMV gathering fp16 pre-relu'd r.
//    Edge stream uses __ldcs (evict-first) so it does not pollute L1;
//    gathers use __ldg and benefit from the halved (400KB) working set.
__global__ void k_step(const float*  __restrict__ vold, float* __restrict__ vnew,
                       const __half* __restrict__ rold, __half* __restrict__ rnew,
                       const float*  __restrict__ table_next,
                       const float*  __restrict__ tau, const float* __restrict__ vrest,
                       int n_neurons, int n_tm1, int copy_blocks) {
    int bid = blockIdx.x;
    if (bid < copy_blocks) {
        int i = bid * blockDim.x + threadIdx.x;
        if (i < n_tm1) {
            float tv = table_next[i];
            vnew[i] = tv;
            rnew[i] = __float2half(fmaxf(tv, 0.0f));
        }
        return;
    }
    int group = threadIdx.x >> 3;        // 32 groups of 8 lanes per 256-thread block
    int lane8 = threadIdx.x & 7;
    int row = n_tm1 + (bid - copy_blocks) * 32 + group;
    if (row >= n_neurons) return;

    int s = g_row_ptr[row];
    int e = g_row_ptr[row + 1];
    float sum = 0.0f;
    int j = s + lane8;
    for (; j + 24 < e; j += 32) {
        int2 e0 = __ldcs(&g_edges[j]);
        int2 e1 = __ldcs(&g_edges[j + 8]);
        int2 e2 = __ldcs(&g_edges[j + 16]);
        int2 e3 = __ldcs(&g_edges[j + 24]);
        float r0 = __half2float(__ldg(&rold[e0.x]));
        float r1 = __half2float(__ldg(&rold[e1.x]));
        float r2 = __half2float(__ldg(&rold[e2.x]));
        float r3 = __half2float(__ldg(&rold[e3.x]));
        sum += __int_as_float(e0.y) * r0;
        sum += __int_as_float(e1.y) * r1;
        sum += __int_as_float(e2.y) * r2;
        sum += __int_as_float(e3.y) * r3;
    }
    for (; j < e; j += 8) {
        int2 ed = __ldcs(&g_edges[j]);
        sum += __int_as_float(ed.y) * __half2float(__ldg(&rold[ed.x]));
    }
    sum += __shfl_xor_sync(0xffffffffu, sum, 4);
    sum += __shfl_xor_sync(0xffffffffu, sum, 2);
    sum += __shfl_xor_sync(0xffffffffu, sum, 1);
    if (lane8 == 0) {
        float vv = vold[row];
        float vn = vv + DT * ((sum - vv + vrest[row]) / tau[row]);
        vnew[row] = vn;
        rnew[row] = __float2half(fmaxf(vn, 0.0f));
    }
}

__global__ void k_out(float* __restrict__ out, const float* __restrict__ vfinal,
                      int n, int n_tm1, int steps) {
    int i = blockIdx.x * blockDim.x + threadIdx.x;
    if (i >= n) return;
    out[i] = (i < n_tm1) ? g_table[(steps - 1) * n_tm1 + i] : vfinal[i];
}

// ---------------- launch ----------------

extern "C" void kernel_launch(void* const* d_in, const int* in_sizes, int n_in,
                              void* d_out, int out_size) {
    const float* tm1_input = (const float*)d_in[0];   // [steps, n_tm1]
    const float* weights   = (const float*)d_in[1];   // [n_edges]
    const float* tau       = (const float*)d_in[2];   // [n_neurons]
    const float* vrest     = (const float*)d_in[3];   // [n_neurons]
    const int*   src       = (const int*)  d_in[4];   // [n_edges]
    const int*   tgt       = (const int*)  d_in[5];   // [n_edges]

    const int n_tm1     = 25000;
    const int n_edges   = in_sizes[1];
    const int n_neurons = in_sizes[2];
    const int steps     = in_sizes[0] / n_tm1;

    const int TPB = 256;
    int nb_neu  = (n_neurons + TPB - 1) / TPB;
    int nb_edge = (n_edges + TPB - 1) / TPB;
    int scan_blocks = (n_neurons + 1023) / 1024;

    // one-time (per launch) setup: zero state, Tm1 trajectory, CSR build by target
    k_init<<<nb_neu, TPB>>>(n_neurons);
    k_tm1<<<(n_tm1 + TPB - 1) / TPB, TPB>>>(tm1_input, n_tm1, steps);
    k_hist<<<nb_edge, TPB>>>(tgt, n_edges, n_tm1);
    k_scan1<<<scan_blocks, 1024>>>(n_neurons);
    k_scan2<<<1, 32>>>(scan_blocks);
    k_scan3<<<nb_neu, TPB>>>(n_neurons, scan_blocks);
    k_fill<<<nb_edge, TPB>>>(src, tgt, weights, n_edges, n_tm1);

    // resolve device-symbol base addresses once
    static float*  vbase = nullptr;
    static __half* rbase = nullptr;
    static float*  tbl   = nullptr;
    if (!vbase) cudaGetSymbolAddress((void**)&vbase, g_vbuf);
    if (!rbase) cudaGetSymbolAddress((void**)&rbase, g_rbuf);
    if (!tbl)   cudaGetSymbolAddress((void**)&tbl,   g_table);

    // time loop: ONE kernel per step
    int rows = n_neurons - n_tm1;
    int copy_blocks = (n_tm1 + TPB - 1) / TPB;
    int spmv_blocks = (rows + 31) / 32;            // 32 rows per block (8 lanes/row)
    int nb_step = copy_blocks + spmv_blocks;

    for (int st = 0; st < steps; st++) {
        const float*  vold = vbase + (size_t)(st & 1) * N_NEURONS_MAX;
        float*        vnew = vbase + (size_t)((st + 1) & 1) * N_NEURONS_MAX;
        const __half* rold = rbase + (size_t)(st & 1) * N_NEURONS_MAX;
        __half*       rnew = rbase + (size_t)((st + 1) & 1) * N_NEURONS_MAX;
        const float* table_next = tbl + (size_t)(st + 1) * n_tm1;
        k_step<<<nb_step, TPB>>>(vold, vnew, rold, rnew, table_next, tau, vrest,
                                 n_neurons, n_tm1, copy_blocks);
    }

    const float* vfinal = vbase + (size_t)(steps & 1) * N_NEURONS_MAX;
    k_out<<<(out_size + TPB - 1) / TPB, TPB>>>((float*)d_out, vfinal,
                                               out_size, n_tm1, steps);
}